// round 15
// baseline (speedup 1.0000x reference)
#include <cuda_runtime.h>
#include <cuda_fp16.h>
#include <cstdint>

#define NN 200000
#define DD 64
#define RR 32
#define BB 16
#define EE 3200000
#define TT 100000
#define KTOT (BB * DD + DD)   // 1088

// fused-layer tiling
#define NODES_BLK 64
#define THREADS 512           // 16 warps
#define NPW 4                 // nodes per warp (strip)
#define ASTR 1096             // sA row stride (halves)
#define BRS 72                // B stage row stride (halves)
#define NBSTAGES (KTOT / 64)  // 17
#define SA_BYTES   (NODES_BLK * ASTR * 2)      // 140288
#define B_STG_B    (64 * BRS * 2)              // 9216
#define OFF_B      SA_BYTES
#define OFF_HST    (OFF_B + 2 * B_STG_B)       // 158720
#define HSTR 72
#define CSTR 24
#define OFF_CST    (OFF_HST + 16 * 16 * HSTR * 2)   // 195584
#define SMEM_TOTAL (OFF_CST + 16 * 16 * CSTR * 2)   // 207872

// ---------------- device scratch (static: allocation-free) ----------------
__device__ __half  g_hp16[(size_t)NN * DD];   // embed fp16, natural layout
__device__ __half  g_h1[(size_t)NN * DD];     // layer-0 out fp16
__device__ float   g_h2[(size_t)NN * DD];     // layer-1 out fp32
__device__ int     g_indeg[NN];
__device__ int     g_off[NN + 1];
__device__ int     g_cursor[NN];
__device__ int2    g_edge[EE];                // (src, etype) sorted by dst
__device__ __half  g_WcT0[DD * KTOT];         // B^T [n][k], fp16
__device__ __half  g_WcT1[DD * KTOT];
__device__ int     g_done;                    // hist ticket

#define CP_ASYNC16(dst32, src) \
    asm volatile("cp.async.cg.shared.global [%0], [%1], 16;" :: "r"(dst32), "l"(src))
#define LDSM_X4_T(r0, r1, r2, r3, addr) \
    asm volatile("ldmatrix.sync.aligned.m8n8.x4.trans.shared.b16 {%0,%1,%2,%3}, [%4];" \
                 : "=r"(r0), "=r"(r1), "=r"(r2), "=r"(r3) : "r"(addr))
#define MMA16816(c, a0, a1, a2, a3, b0, b1) \
    asm volatile("mma.sync.aligned.m16n8k16.row.col.f32.f16.f16.f32 " \
                 "{%0,%1,%2,%3}, {%4,%5,%6,%7}, {%8,%9}, {%0,%1,%2,%3};\n" \
                 : "+f"((c)[0]), "+f"((c)[1]), "+f"((c)[2]), "+f"((c)[3]) \
                 : "r"(a0), "r"(a1), "r"(a2), "r"(a3), "r"(b0), "r"(b1))

__device__ __forceinline__ int swz(int c) { return c ^ ((c >> 3) & 7); }

// ---------------- prep_all ----------------
__global__ void prep_all_kernel(const float* __restrict__ embed,
                                const float* __restrict__ v0, const float* __restrict__ wl0,
                                const float* __restrict__ v1, const float* __restrict__ wl1,
                                int n) {
    int tid = blockIdx.x * blockDim.x + threadIdx.x;
    int stride = gridDim.x * blockDim.x;
    if (tid == 0) g_done = 0;
    for (int i = tid; i < n * 32; i += stride) {
        float2 v = ((const float2*)embed)[i];
        ((__half2*)g_hp16)[i] = __floats2half2_rn(v.x, v.y);
    }
    for (int i = tid; i < DD * KTOT; i += stride) {
        int nn = i / KTOT, k = i - nn * KTOT;
        float a, b;
        if (k < BB * DD) {
            int bidx = k >> 6, d = k & 63;
            a = v0[bidx * DD * DD + d * DD + nn];
            b = v1[bidx * DD * DD + d * DD + nn];
        } else {
            int d = k - BB * DD;
            a = wl0[d * DD + nn];
            b = wl1[d * DD + nn];
        }
        g_WcT0[i] = __float2half_rn(a);
        g_WcT1[i] = __float2half_rn(b);
    }
    for (int i = tid; i < n; i += stride) g_indeg[i] = 0;
}

// ---------------- hist + scan (last-block ticket runs the scan) ----------------
__global__ void hist_scan_kernel(const int* __restrict__ dst, int e_cnt, int n) {
    for (int e = blockIdx.x * blockDim.x + threadIdx.x; e < e_cnt; e += gridDim.x * blockDim.x)
        atomicAdd(&g_indeg[dst[e]], 1);
    __syncthreads();
    __threadfence();
    __shared__ int is_last;
    if (threadIdx.x == 0)
        is_last = (atomicAdd(&g_done, 1) == (int)gridDim.x - 1);
    __syncthreads();
    if (!is_last) return;

    __shared__ int warpsum[32];
    __shared__ int s_carry;
    int t = threadIdx.x, lane = t & 31, w = t >> 5;
    if (t == 0) s_carry = 0;
    __syncthreads();
    for (int base = 0; base < n; base += 1024) {
        int i = base + t;
        int v = (i < n) ? __ldcg(&g_indeg[i]) : 0;
        int x = v;
        #pragma unroll
        for (int d = 1; d < 32; d <<= 1) {
            int y = __shfl_up_sync(0xffffffffu, x, d);
            if (lane >= d) x += y;
        }
        if (lane == 31) warpsum[w] = x;
        __syncthreads();
        if (w == 0) {
            int s = warpsum[lane];
            #pragma unroll
            for (int d = 1; d < 32; d <<= 1) {
                int y = __shfl_up_sync(0xffffffffu, s, d);
                if (lane >= d) s += y;
            }
            warpsum[lane] = s;
        }
        __syncthreads();
        int excl = s_carry + x - v + (w ? warpsum[w - 1] : 0);
        if (i < n) { g_off[i] = excl; g_cursor[i] = excl; }
        int tot = warpsum[31];
        __syncthreads();
        if (t == 0) s_carry += tot;
        __syncthreads();
    }
    if (t == 0) g_off[n] = s_carry;
}

__global__ void scatter_kernel(const int* __restrict__ src, const int* __restrict__ dst,
                               const int* __restrict__ et, int e_cnt) {
    for (int e = blockIdx.x * blockDim.x + threadIdx.x; e < e_cnt; e += gridDim.x * blockDim.x) {
        int p = atomicAdd(&g_cursor[dst[e]], 1);
        g_edge[p] = make_int2(src[e], et[e]);
    }
}

// ------------- fused layer: strip-pipelined TC aggregation -> sA -> block GEMM --------
__global__ void __launch_bounds__(THREADS, 1)
fused_layer_kernel(const float* __restrict__ cmat, const float* __restrict__ bias,
                   int layer, int n_nodes) {
    extern __shared__ __align__(16) char sm[];
    __shared__ __align__(16) __half c16[33 * 16];   // row 32 = zeros (padding rows)
    __half* sA = (__half*)sm;
    const __half* __restrict__ hin = (layer == 0) ? g_hp16 : g_h1;
    const __half* __restrict__ Bt  = (layer == 0) ? g_WcT0 : g_WcT1;

    int t = threadIdx.x, w = t >> 5, lane = t & 31;
    int g = lane >> 2, tig = lane & 3;
    int blockRow = blockIdx.x * NODES_BLK;

    // prefetch B stage 0 (hidden under aggregation)
    {
        int nr = t >> 3, seg = t & 7;
        const __half* srcp = Bt + (size_t)nr * KTOT + seg * 8;
        uint32_t dstp = (uint32_t)__cvta_generic_to_shared(sm + OFF_B + (nr * BRS + seg * 8) * 2);
        CP_ASYNC16(dstp, srcp);
        asm volatile("cp.async.commit_group;");
    }

    for (int i = t; i < 32 * 16; i += THREADS) c16[i] = __float2half_rn(cmat[i]);
    for (int i = 32 * 16 + t; i < 33 * 16; i += THREADS) c16[i] = __ushort_as_half(0);
    __syncthreads();

    // ---- aggregation phase: warp strip of NPW nodes, cross-node prefetch pipeline ----
    {
        int n0 = blockRow + w * NPW;
        int rsub = lane >> 3;
        int seg  = lane & 7;
        int crow = lane >> 1, cpart = lane & 1;

        uint32_t hb = (uint32_t)__cvta_generic_to_shared(sm + OFF_HST + w * 16 * HSTR * 2);
        uint32_t cb = (uint32_t)__cvta_generic_to_shared(sm + OFF_CST + w * 16 * CSTR * 2);
        uint32_t aaddr = cb + (uint32_t)((((lane & 7) + ((lane & 16) >> 1)) * CSTR + (lane & 8)) * 2);
        uint32_t baddr = hb + (uint32_t)(((lane & 15) * HSTR + ((lane & 16) >> 1)) * 2);
        __half* hstw = (__half*)(sm + OFF_HST + w * 16 * HSTR * 2);
        __half* cstw = (__half*)(sm + OFF_CST + w * 16 * CSTR * 2);

        if (n0 < n_nodes) {
            int offv = g_off[min(n0 + min(lane, NPW), n_nodes)];
            int beg[NPW], end[NPW];
            #pragma unroll
            for (int i = 0; i < NPW; i++) {
                beg[i] = __shfl_sync(0xffffffffu, offv, i);
                end[i] = __shfl_sync(0xffffffffu, offv, i + 1);
            }

            uint4 hv[4]; uint4 cv;
            auto fetch = [&](int ni, int kc) {
                int e_ = end[ni];
                int ei = kc + (lane & 15);
                int ec = (ei < e_) ? ei : e_ - 1;
                int2 e = g_edge[ec];
                int rsel = (ei < e_) ? e.y : 32;
                #pragma unroll
                for (int rep = 0; rep < 4; rep++) {
                    int r = rep * 4 + rsub;
                    int s = __shfl_sync(0xffffffffu, e.x, r);
                    hv[rep] = *(const uint4*)(hin + (size_t)s * DD + seg * 8);
                }
                int rc = __shfl_sync(0xffffffffu, rsel, crow);
                cv = *(const uint4*)(c16 + rc * 16 + cpart * 8);
            };

            int cni = 0;
            while (cni < NPW && beg[cni] >= end[cni]) cni++;
            int ckc = (cni < NPW) ? beg[cni] : 0;
            if (cni < NPW) fetch(cni, ckc);

            #pragma unroll 1
            for (int i = 0; i < NPW; i++) {
                int n = n0 + i;
                if (n >= n_nodes) break;

                uint32_t selfv = ((const uint32_t*)(hin + (size_t)n * DD))[lane];

                float acc[8][4];
                #pragma unroll
                for (int a = 0; a < 8; a++)
                    #pragma unroll
                    for (int b = 0; b < 4; b++) acc[a][b] = 0.f;

                #pragma unroll 1
                for (int kc = beg[i]; kc < end[i]; kc += 16) {
                    #pragma unroll
                    for (int rep = 0; rep < 4; rep++) {
                        int r = rep * 4 + rsub;
                        *(uint4*)(hstw + r * HSTR + seg * 8) = hv[rep];
                    }
                    *(uint4*)(cstw + crow * CSTR + cpart * 8) = cv;
                    ckc += 16;
                    if (ckc >= end[cni]) {
                        cni++;
                        while (cni < NPW && beg[cni] >= end[cni]) cni++;
                        ckc = (cni < NPW) ? beg[cni] : 0;
                    }
                    if (cni < NPW) fetch(cni, ckc);
                    __syncwarp();
                    uint32_t a0, a1, a2, a3;
                    LDSM_X4_T(a0, a1, a2, a3, aaddr);
                    #pragma unroll
                    for (int dt = 0; dt < 4; dt++) {
                        uint32_t b0, b1, b2, b3;
                        LDSM_X4_T(b0, b1, b2, b3, baddr + dt * 32);
                        MMA16816(acc[2 * dt],     a0, a1, a2, a3, b0, b1);
                        MMA16816(acc[2 * dt + 1], a0, a1, a2, a3, b2, b3);
                    }
                    __syncwarp();
                }

                // deposit swizzled A row directly into sA (no global round-trip)
                int local = w * NPW + i;
                __half* arow = sA + (size_t)local * ASTR;
                #pragma unroll
                for (int dt = 0; dt < 8; dt++) {
                    int p0 = (g * 8 + (dt ^ g)) * 8 + 2 * tig;          // b = g
                    int p1 = ((g + 8) * 8 + (dt ^ g)) * 8 + 2 * tig;    // b = g+8
                    *(__half2*)(arow + p0) = __floats2half2_rn(acc[dt][0], acc[dt][1]);
                    *(__half2*)(arow + p1) = __floats2half2_rn(acc[dt][2], acc[dt][3]);
                }
                *(uint32_t*)(arow + 1024 + 2 * lane) = selfv;   // chunk 128+g: swz identity
            }
        }
    }
    __syncthreads();

    // ---- GEMM phase: (64 x 1088) @ (1088 x 64), 16 warps m16n16 ----
    int wr = w >> 2, wc = w & 3;
    float c[2][4];
    #pragma unroll
    for (int nb = 0; nb < 2; nb++)
        #pragma unroll
        for (int q = 0; q < 4; q++) c[nb][q] = 0.f;

    int arow0 = (wr * 16 + g) * ASTR;

    #pragma unroll 1
    for (int ks = 0; ks < NBSTAGES; ks++) {
        if (ks + 1 < NBSTAGES) {
            int nr = t >> 3, seg = t & 7;
            const __half* srcp = Bt + (size_t)nr * KTOT + (ks + 1) * 64 + seg * 8;
            uint32_t dstp = (uint32_t)__cvta_generic_to_shared(
                sm + OFF_B + ((ks + 1) & 1) * B_STG_B + (nr * BRS + seg * 8) * 2);
            CP_ASYNC16(dstp, srcp);
        }
        asm volatile("cp.async.commit_group;");
        asm volatile("cp.async.wait_group 1;");
        __syncthreads();

        const __half* Bs = (const __half*)(sm + OFF_B + (ks & 1) * B_STG_B);
        #pragma unroll
        for (int k16 = 0; k16 < 4; k16++) {
            int kb = ks * 64 + k16 * 16;
            int c0 = kb >> 3;
            int p0 = swz(c0) * 8 + 2 * tig;
            int p1 = swz(c0 + 1) * 8 + 2 * tig;
            uint32_t a0 = *(const uint32_t*)(sA + arow0 + p0);
            uint32_t a1 = *(const uint32_t*)(sA + arow0 + 8 * ASTR + p0);
            uint32_t a2 = *(const uint32_t*)(sA + arow0 + p1);
            uint32_t a3 = *(const uint32_t*)(sA + arow0 + 8 * ASTR + p1);
            #pragma unroll
            for (int nb = 0; nb < 2; nb++) {
                const __half* bb = Bs + (wc * 16 + nb * 8 + g) * BRS + k16 * 16 + 2 * tig;
                uint32_t b0 = *(const uint32_t*)(bb);
                uint32_t b1 = *(const uint32_t*)(bb + 8);
                MMA16816(c[nb], a0, a1, a2, a3, b0, b1);
            }
        }
        __syncthreads();
    }

    // epilogue: bias (+relu); layer0 -> fp16 g_h1, layer1 -> fp32 g_h2
    #pragma unroll
    for (int nb = 0; nb < 2; nb++) {
        int colb = wc * 16 + nb * 8 + 2 * tig;
        int row0 = blockRow + wr * 16 + g;
        float bb0 = bias[colb], bb1 = bias[colb + 1];
        float v00 = c[nb][0] + bb0, v01 = c[nb][1] + bb1;
        float v10 = c[nb][2] + bb0, v11 = c[nb][3] + bb1;
        if (layer == 0) {
            v00 = fmaxf(v00, 0.f); v01 = fmaxf(v01, 0.f);
            v10 = fmaxf(v10, 0.f); v11 = fmaxf(v11, 0.f);
            if (row0 < n_nodes)
                *(__half2*)(g_h1 + (size_t)row0 * DD + colb) = __floats2half2_rn(v00, v01);
            if (row0 + 8 < n_nodes)
                *(__half2*)(g_h1 + (size_t)(row0 + 8) * DD + colb) = __floats2half2_rn(v10, v11);
        } else {
            if (row0 < n_nodes)
                *(float2*)(g_h2 + (size_t)row0 * DD + colb) = make_float2(v00, v01);
            if (row0 + 8 < n_nodes)
                *(float2*)(g_h2 + (size_t)(row0 + 8) * DD + colb) = make_float2(v10, v11);
        }
    }
}

// ---------------- DistMult scoring: warp per triplet ----------------
__global__ void score_kernel(const int* __restrict__ head, const int* __restrict__ rel,
                             const int* __restrict__ tail, const float* __restrict__ wrel,
                             float* __restrict__ out, int t_cnt) {
    int w = (blockIdx.x * blockDim.x + threadIdx.x) >> 5;
    int lane = threadIdx.x & 31;
    if (w >= t_cnt) return;
    float2 a = *(const float2*)(g_h2 + (size_t)head[w] * DD + 2 * lane);
    float2 r = *(const float2*)(wrel + (size_t)rel[w] * DD + 2 * lane);
    float2 b = *(const float2*)(g_h2 + (size_t)tail[w] * DD + 2 * lane);
    float p = a.x * r.x * b.x + a.y * r.y * b.y;
    #pragma unroll
    for (int d = 16; d > 0; d >>= 1) p += __shfl_xor_sync(0xffffffffu, p, d);
    if (lane == 0) out[w] = p;
}

// ---------------- launch ----------------
extern "C" void kernel_launch(void* const* d_in, const int* in_sizes, int n_in,
                              void* d_out, int out_size) {
    const int*   src   = (const int*)d_in[0];
    const int*   dst   = (const int*)d_in[1];
    const int*   ety   = (const int*)d_in[2];
    const int*   head  = (const int*)d_in[3];
    const int*   rel   = (const int*)d_in[4];
    const int*   tail  = (const int*)d_in[5];
    const float* embed = (const float*)d_in[6];
    const float* v0    = (const float*)d_in[7];
    const float* c0    = (const float*)d_in[8];
    const float* wl0   = (const float*)d_in[9];
    const float* b0    = (const float*)d_in[10];
    const float* v1    = (const float*)d_in[11];
    const float* c1    = (const float*)d_in[12];
    const float* wl1   = (const float*)d_in[13];
    const float* b1    = (const float*)d_in[14];
    const float* wrel  = (const float*)d_in[15];
    float* out = (float*)d_out;

    int E = in_sizes[0];
    int T = in_sizes[3];
    int N = in_sizes[6] / DD;
    if (N > NN) N = NN;
    if (E > EE) E = EE;
    if (T > TT) T = TT;

    cudaFuncSetAttribute(fused_layer_kernel,
                         cudaFuncAttributeMaxDynamicSharedMemorySize, SMEM_TOTAL);

    prep_all_kernel<<<2048, 256>>>(embed, v0, wl0, v1, wl1, N);   // (0)
    hist_scan_kernel<<<256, 1024>>>(dst, E, N);                   // (1)
    scatter_kernel<<<1024, 256>>>(src, dst, ety, E);              // (2)

    int grid = (N + NODES_BLK - 1) / NODES_BLK;
    fused_layer_kernel<<<grid, THREADS, SMEM_TOTAL>>>(c0, b0, 0, N);   // (3) layer 0
    fused_layer_kernel<<<grid, THREADS, SMEM_TOTAL>>>(c1, b1, 1, N);   // (4) layer 1

    // DistMult scoring
    score_kernel<<<(T + 7) / 8, 256>>>(head, rel, tail, wrel, out, T); // (5)
}

// round 16
// speedup vs baseline: 1.4048x; 1.4048x over previous
#include <cuda_runtime.h>
#include <cuda_fp16.h>
#include <cstdint>

#define NN 200000
#define DD 64
#define RR 32
#define BB 16
#define EE 3200000
#define TT 100000
#define KTOT (BB * DD + DD)   // 1088

// GEMM tiling
#define BM 128
#define BK 64
#define NKSTAGES (KTOT / BK)  // 17
#define ARS 72
#define A_STG_BYTES (BM * ARS * 2)
#define B_STG_BYTES (64 * ARS * 2)
#define SMEM_GEMM (2 * A_STG_BYTES + 2 * B_STG_BYTES)  // 55296

// aggregation staging
#define AGG_WARPS 8
#define NPW 4       // nodes per warp (strip, pipelined across nodes)
#define HSTR 72
#define CSTR 24

#define SCAN_BLK 1024
#define NSCAN_BLKS ((NN + SCAN_BLK - 1) / SCAN_BLK)   // 196

// ---------------- device scratch (static: allocation-free) ----------------
__device__ __half  g_acc[(size_t)NN * KTOT];  // (N,1088) accumulator rows, fp16
__device__ __half  g_hp16[(size_t)NN * DD];   // embed fp16, natural layout
__device__ __half  g_h1[(size_t)NN * DD];     // layer-0 out fp16
__device__ float   g_h2[(size_t)NN * DD];     // layer-1 out fp32
__device__ int     g_indeg[NN];
__device__ int     g_off[NN + 1];
__device__ int     g_cursor[NN];
__device__ int     g_bsum[256];               // scan block sums
__device__ int2    g_edge[EE];                // (src, etype) sorted by dst
__device__ __half  g_WcT0[DD * KTOT];         // B^T [n][k], fp16
__device__ __half  g_WcT1[DD * KTOT];

#define CP_ASYNC16(dst32, src) \
    asm volatile("cp.async.cg.shared.global [%0], [%1], 16;" :: "r"(dst32), "l"(src))
#define CP_ASYNC16Z(dst32, src, sz) \
    asm volatile("cp.async.cg.shared.global [%0], [%1], 16, %2;" :: "r"(dst32), "l"(src), "r"(sz))
#define LDSM_X4_T(r0, r1, r2, r3, addr) \
    asm volatile("ldmatrix.sync.aligned.m8n8.x4.trans.shared.b16 {%0,%1,%2,%3}, [%4];" \
                 : "=r"(r0), "=r"(r1), "=r"(r2), "=r"(r3) : "r"(addr))
#define MMA16816(c, a0, a1, a2, a3, b0, b1) \
    asm volatile("mma.sync.aligned.m16n8k16.row.col.f32.f16.f16.f32 " \
                 "{%0,%1,%2,%3}, {%4,%5,%6,%7}, {%8,%9}, {%0,%1,%2,%3};\n" \
                 : "+f"((c)[0]), "+f"((c)[1]), "+f"((c)[2]), "+f"((c)[3]) \
                 : "r"(a0), "r"(a1), "r"(a2), "r"(a3), "r"(b0), "r"(b1))

// ---------------- prep_all ----------------
__global__ void prep_all_kernel(const float* __restrict__ embed,
                                const float* __restrict__ v0, const float* __restrict__ wl0,
                                const float* __restrict__ v1, const float* __restrict__ wl1,
                                int n) {
    int tid = blockIdx.x * blockDim.x + threadIdx.x;
    int stride = gridDim.x * blockDim.x;
    for (int i = tid; i < n * 32; i += stride) {
        float2 v = ((const float2*)embed)[i];
        ((__half2*)g_hp16)[i] = __floats2half2_rn(v.x, v.y);
    }
    for (int i = tid; i < DD * KTOT; i += stride) {
        int nn = i / KTOT, k = i - nn * KTOT;
        float a, b;
        if (k < BB * DD) {
            int bidx = k >> 6, d = k & 63;
            a = v0[bidx * DD * DD + d * DD + nn];
            b = v1[bidx * DD * DD + d * DD + nn];
        } else {
            int d = k - BB * DD;
            a = wl0[d * DD + nn];
            b = wl1[d * DD + nn];
        }
        g_WcT0[i] = __float2half_rn(a);
        g_WcT1[i] = __float2half_rn(b);
    }
    for (int i = tid; i < n; i += stride) g_indeg[i] = 0;
}

// ---------------- histogram ----------------
__global__ void hist_kernel(const int* __restrict__ dst, int e_cnt) {
    for (int e = blockIdx.x * blockDim.x + threadIdx.x; e < e_cnt; e += gridDim.x * blockDim.x)
        atomicAdd(&g_indeg[dst[e]], 1);
}

// ---------------- parallel exclusive scan (3 phases) ----------------
__global__ void scan1_kernel(int n) {          // block-local exclusive scan + block sums
    __shared__ int wsum[32];
    int t = threadIdx.x, lane = t & 31, w = t >> 5;
    int i = blockIdx.x * SCAN_BLK + t;
    int v = (i < n) ? g_indeg[i] : 0;
    int x = v;
    #pragma unroll
    for (int d = 1; d < 32; d <<= 1) {
        int y = __shfl_up_sync(0xffffffffu, x, d);
        if (lane >= d) x += y;
    }
    if (lane == 31) wsum[w] = x;
    __syncthreads();
    if (w == 0) {
        int s = wsum[lane];
        #pragma unroll
        for (int d = 1; d < 32; d <<= 1) {
            int y = __shfl_up_sync(0xffffffffu, s, d);
            if (lane >= d) s += y;
        }
        wsum[lane] = s;
    }
    __syncthreads();
    int excl = x - v + (w ? wsum[w - 1] : 0);
    if (i < n) g_off[i] = excl;
    if (t == SCAN_BLK - 1) g_bsum[blockIdx.x] = excl + v;
}

__global__ void scan2_kernel(int nb) {         // single block: scan block sums (nb<=256)
    __shared__ int wsum[8];
    int t = threadIdx.x, lane = t & 31, w = t >> 5;
    int v = (t < nb) ? g_bsum[t] : 0;
    int x = v;
    #pragma unroll
    for (int d = 1; d < 32; d <<= 1) {
        int y = __shfl_up_sync(0xffffffffu, x, d);
        if (lane >= d) x += y;
    }
    if (lane == 31) wsum[w] = x;
    __syncthreads();
    if (w == 0 && lane < 8) {
        int s = wsum[lane];
        #pragma unroll
        for (int d = 1; d < 8; d <<= 1) {
            int y = __shfl_up_sync(0xffu, s, d);
            if (lane >= d) s += y;
        }
        wsum[lane] = s;
    }
    __syncthreads();
    int excl = x - v + (w ? wsum[w - 1] : 0);
    if (t < nb) g_bsum[t] = excl;
}

__global__ void scan3_kernel(int n, int e) {   // add block bases; init cursor; total
    int i = blockIdx.x * SCAN_BLK + threadIdx.x;
    if (i < n) {
        int o = g_off[i] + g_bsum[blockIdx.x];
        g_off[i] = o;
        g_cursor[i] = o;
    }
    if (i == 0) g_off[n] = e;
}

__global__ void scatter_kernel(const int* __restrict__ src, const int* __restrict__ dst,
                               const int* __restrict__ et, int e_cnt) {
    for (int e = blockIdx.x * blockDim.x + threadIdx.x; e < e_cnt; e += gridDim.x * blockDim.x) {
        int p = atomicAdd(&g_cursor[dst[e]], 1);
        g_edge[p] = make_int2(src[e], et[e]);
    }
}

// ---------------- TC aggregation: warp per 4-node strip, cross-node pipeline ----------
__global__ void __launch_bounds__(256, 3)
aggregate_kernel(const float* __restrict__ cmat, int layer, int n_nodes) {
    __shared__ __align__(16) __half c16[33 * 16];
    __shared__ __align__(16) __half hst[AGG_WARPS][17 * HSTR];   // 16 stage rows + wb row
    __shared__ __align__(16) __half cst[AGG_WARPS][16 * CSTR];
    const __half* __restrict__ hin = (layer == 0) ? g_hp16 : g_h1;
    int t = threadIdx.x, w = t >> 5, lane = t & 31;

    for (int i = t; i < 32 * 16; i += 256) c16[i] = __float2half_rn(cmat[i]);
    for (int i = 32 * 16 + t; i < 33 * 16; i += 256) c16[i] = __ushort_as_half(0);
    __syncthreads();

    int n0 = (blockIdx.x * AGG_WARPS + w) * NPW;
    if (n0 >= n_nodes) return;

    int g = lane >> 2, tig = lane & 3;
    int rsub = lane >> 3;
    int seg  = lane & 7;
    int crow = lane >> 1, cpart = lane & 1;

    uint32_t hb = (uint32_t)__cvta_generic_to_shared(hst[w]);
    uint32_t cb = (uint32_t)__cvta_generic_to_shared(cst[w]);
    uint32_t aaddr = cb + (uint32_t)((((lane & 7) + ((lane & 16) >> 1)) * CSTR + (lane & 8)) * 2);
    uint32_t baddr = hb + (uint32_t)(((lane & 15) * HSTR + ((lane & 16) >> 1)) * 2);

    // strip offsets: one coalesced LDG + shfl
    int offv = g_off[min(n0 + min(lane, NPW), n_nodes)];
    int beg[NPW], end[NPW];
    #pragma unroll
    for (int i = 0; i < NPW; i++) {
        beg[i] = __shfl_sync(0xffffffffu, offv, i);
        end[i] = __shfl_sync(0xffffffffu, offv, i + 1);
    }

    uint4 hv[4]; uint4 cv;
    auto fetch = [&](int ni, int kc) {
        int e_ = end[ni];
        int ei = kc + (lane & 15);
        int ec = (ei < e_) ? ei : e_ - 1;
        int2 e = g_edge[ec];
        int rsel = (ei < e_) ? e.y : 32;
        #pragma unroll
        for (int rep = 0; rep < 4; rep++) {
            int r = rep * 4 + rsub;
            int s = __shfl_sync(0xffffffffu, e.x, r);
            hv[rep] = *(const uint4*)(hin + (size_t)s * DD + seg * 8);
        }
        int rc = __shfl_sync(0xffffffffu, rsel, crow);
        cv = *(const uint4*)(c16 + rc * 16 + cpart * 8);
    };

    // cursor over the strip's chunk stream (warp-uniform)
    int cni = 0;
    while (cni < NPW && beg[cni] >= end[cni]) cni++;
    int ckc = (cni < NPW) ? beg[cni] : 0;
    if (cni < NPW) fetch(cni, ckc);

    #pragma unroll 1
    for (int i = 0; i < NPW; i++) {
        int n = n0 + i;
        if (n >= n_nodes) break;

        // self-loop row: independent LDG, issue early
        uint32_t selfv = ((const uint32_t*)(hin + (size_t)n * DD))[lane];

        float acc[8][4];
        #pragma unroll
        for (int a = 0; a < 8; a++)
            #pragma unroll
            for (int b = 0; b < 4; b++) acc[a][b] = 0.f;

        #pragma unroll 1
        for (int kc = beg[i]; kc < end[i]; kc += 16) {
            // invariant: prefetched regs hold chunk (i, kc)
            #pragma unroll
            for (int rep = 0; rep < 4; rep++) {
                int r = rep * 4 + rsub;
                *(uint4*)(hst[w] + r * HSTR + seg * 8) = hv[rep];
            }
            *(uint4*)(cst[w] + crow * CSTR + cpart * 8) = cv;
            // advance cursor and prefetch (may bridge into the next node)
            ckc += 16;
            if (ckc >= end[cni]) {
                cni++;
                while (cni < NPW && beg[cni] >= end[cni]) cni++;
                ckc = (cni < NPW) ? beg[cni] : 0;
            }
            if (cni < NPW) fetch(cni, ckc);
            __syncwarp();
            uint32_t a0, a1, a2, a3;
            LDSM_X4_T(a0, a1, a2, a3, aaddr);
            #pragma unroll
            for (int dt = 0; dt < 4; dt++) {
                uint32_t b0, b1, b2, b3;
                LDSM_X4_T(b0, b1, b2, b3, baddr + dt * 32);
                MMA16816(acc[2 * dt],     a0, a1, a2, a3, b0, b1);
                MMA16816(acc[2 * dt + 1], a0, a1, a2, a3, b2, b3);
            }
            __syncwarp();
        }

        // coalesced writeback: fragments -> smem rows (stride 72) -> contiguous STG.128
        __half* buf = hst[w];
        #pragma unroll
        for (int dt = 0; dt < 8; dt++) {
            int d = dt * 8 + 2 * tig;
            *(__half2*)(buf + g * HSTR + d)       = __floats2half2_rn(acc[dt][0], acc[dt][1]);
            *(__half2*)(buf + (g + 8) * HSTR + d) = __floats2half2_rn(acc[dt][2], acc[dt][3]);
        }
        *(uint32_t*)(buf + 16 * HSTR + 2 * lane) = selfv;
        __syncwarp();
        uint4* arow4 = (uint4*)(g_acc + (size_t)n * KTOT);
        #pragma unroll
        for (int q = lane; q < 136; q += 32)
            arow4[q] = *(const uint4*)(buf + (q >> 3) * HSTR + (q & 7) * 8);
        __syncwarp();   // buf reads done before next node stages into hst
    }
}

// ---------------- pipelined fp16 GEMM: (N,1088) @ (1088,64) + bias (+relu) ------------
__global__ void __launch_bounds__(256)
gemm_kernel(const float* __restrict__ bias, int layer, int nrows) {
    extern __shared__ char sm[];
    const __half* __restrict__ Ag = g_acc;
    const __half* __restrict__ Bt = (layer == 0) ? g_WcT0 : g_WcT1;

    int t = threadIdx.x, w = t >> 5, lane = t & 31;
    int g = lane >> 2, tig = lane & 3;
    int wr = w >> 1, wc = w & 1;
    int blockRow = blockIdx.x * BM;

    float c[2][4][4];
    #pragma unroll
    for (int m2 = 0; m2 < 2; m2++)
        #pragma unroll
        for (int nb = 0; nb < 4; nb++)
            #pragma unroll
            for (int q = 0; q < 4; q++) c[m2][nb][q] = 0.f;

    auto load_stage = [&](int s, int ks) {
        char* As = sm + s * A_STG_BYTES;
        char* Bs = sm + 2 * A_STG_BYTES + s * B_STG_BYTES;
        #pragma unroll
        for (int r = 0; r < 4; r++) {
            int cidx = t + r * 256;
            int rowi = cidx >> 3, seg = cidx & 7;
            int grow = blockRow + rowi;
            int sz = (grow < nrows) ? 16 : 0;
            int gr = (grow < nrows) ? grow : (nrows - 1);
            const __half* src = Ag + (size_t)gr * KTOT + ks * BK + seg * 8;
            uint32_t dsta = (uint32_t)__cvta_generic_to_shared(As + rowi * (ARS * 2) + seg * 16);
            CP_ASYNC16Z(dsta, src, sz);
        }
        #pragma unroll
        for (int r = 0; r < 2; r++) {
            int cidx = t + r * 256;
            int nrow = cidx >> 3, seg = cidx & 7;
            const __half* src = Bt + (size_t)nrow * KTOT + ks * BK + seg * 8;
            uint32_t dstb = (uint32_t)__cvta_generic_to_shared(Bs + nrow * (ARS * 2) + seg * 16);
            CP_ASYNC16(dstb, src);
        }
    };

    load_stage(0, 0);
    asm volatile("cp.async.commit_group;");

    #pragma unroll 1
    for (int ks = 0; ks < NKSTAGES; ks++) {
        if (ks + 1 < NKSTAGES) load_stage((ks + 1) & 1, ks + 1);
        asm volatile("cp.async.commit_group;");
        asm volatile("cp.async.wait_group 1;");
        __syncthreads();

        int s = ks & 1;
        const __half* As = (const __half*)(sm + s * A_STG_BYTES);
        const __half* Bs = (const __half*)(sm + 2 * A_STG_BYTES + s * B_STG_BYTES);
        #pragma unroll
        for (int k16 = 0; k16 < BK / 16; k16++) {
            int kb = k16 * 16;
            uint32_t a[2][4];
            #pragma unroll
            for (int m2 = 0; m2 < 2; m2++) {
                const __half* ab = As + (wr * 32 + m2 * 16 + g) * ARS + kb + 2 * tig;
                a[m2][0] = *(const uint32_t*)(ab);
                a[m2][1] = *(const uint32_t*)(ab + 8 * ARS);
                a[m2][2] = *(const uint32_t*)(ab + 8);
                a[m2][3] = *(const uint32_t*)(ab + 8 * ARS + 8);
            }
            #pragma unroll
            for (int nb = 0; nb < 4; nb++) {
                const __half* bb = Bs + (wc * 32 + nb * 8 + g) * ARS + kb + 2 * tig;
                uint32_t b0 = *(const uint32_t*)(bb);
                uint32_t b1 = *(const uint32_t*)(bb + 8);
                #pragma unroll
                for (int m2 = 0; m2 < 2; m2++)
                    MMA16816(c[m2][nb], a[m2][0], a[m2][1], a[m2][2], a[m2][3], b0, b1);
            }
        }
        __syncthreads();
    }

    #pragma unroll
    for (int m2 = 0; m2 < 2; m2++) {
        #pragma unroll
        for (int nb = 0; nb < 4; nb++) {
            int colb = wc * 32 + nb * 8 + 2 * tig;
            int row0 = blockRow + wr * 32 + m2 * 16 + g;
            float bb0 = bias[colb], bb1 = bias[colb + 1];
            float v00 = c[m2][nb][0] + bb0, v01 = c[m2][nb][1] + bb1;
            float v10 = c[m2][nb][2] + bb0, v11 = c[m2][nb][3] + bb1;
            if (layer == 0) {
                v00 = fmaxf(v00, 0.f); v01 = fmaxf(v01, 0.f);
                v10 = fmaxf(v10, 0.f); v11 = fmaxf(v11, 0.f);
                if (row0 < nrows)
                    *(__half2*)(g_h1 + (size_t)row0 * DD + colb) = __floats2half2_rn(v00, v01);
                if (row0 + 8 < nrows)
                    *(__half2*)(g_h1 + (size_t)(row0 + 8) * DD + colb) = __floats2half2_rn(v10, v11);
            } else {
                if (row0 < nrows)
                    *(float2*)(g_h2 + (size_t)row0 * DD + colb) = make_float2(v00, v01);
                if (row0 + 8 < nrows)
                    *(float2*)(g_h2 + (size_t)(row0 + 8) * DD + colb) = make_float2(v10, v11);
            }
        }
    }
}

// ---------------- DistMult scoring: warp per triplet ----------------
__global__ void score_kernel(const int* __restrict__ head, const int* __restrict__ rel,
                             const int* __restrict__ tail, const float* __restrict__ wrel,
                             float* __restrict__ out, int t_cnt) {
    int w = (blockIdx.x * blockDim.x + threadIdx.x) >> 5;
    int lane = threadIdx.x & 31;
    if (w >= t_cnt) return;
    float2 a = *(const float2*)(g_h2 + (size_t)head[w] * DD + 2 * lane);
    float2 r = *(const float2*)(wrel + (size_t)rel[w] * DD + 2 * lane);
    float2 b = *(const float2*)(g_h2 + (size_t)tail[w] * DD + 2 * lane);
    float p = a.x * r.x * b.x + a.y * r.y * b.y;
    #pragma unroll
    for (int d = 16; d > 0; d >>= 1) p += __shfl_xor_sync(0xffffffffu, p, d);
    if (lane == 0) out[w] = p;
}

// ---------------- launch ----------------
extern "C" void kernel_launch(void* const* d_in, const int* in_sizes, int n_in,
                              void* d_out, int out_size) {
    const int*   src   = (const int*)d_in[0];
    const int*   dst   = (const int*)d_in[1];
    const int*   ety   = (const int*)d_in[2];
    const int*   head  = (const int*)d_in[3];
    const int*   rel   = (const int*)d_in[4];
    const int*   tail  = (const int*)d_in[5];
    const float* embed = (const float*)d_in[6];
    const float* v0    = (const float*)d_in[7];
    const float* c0    = (const float*)d_in[8];
    const float* wl0   = (const float*)d_in[9];
    const float* b0    = (const float*)d_in[10];
    const float* v1    = (const float*)d_in[11];
    const float* c1    = (const float*)d_in[12];
    const float* wl1   = (const float*)d_in[13];
    const float* b1    = (const float*)d_in[14];
    const float* wrel  = (const float*)d_in[15];
    float* out = (float*)d_out;

    int E = in_sizes[0];
    int T = in_sizes[3];
    int N = in_sizes[6] / DD;
    if (N > NN) N = NN;
    if (E > EE) E = EE;
    if (T > TT) T = TT;

    cudaFuncSetAttribute(gemm_kernel,
                         cudaFuncAttributeMaxDynamicSharedMemorySize, SMEM_GEMM);

    int nsb = (N + SCAN_BLK - 1) / SCAN_BLK;
    prep_all_kernel<<<2048, 256>>>(embed, v0, wl0, v1, wl1, N);   // (0)
    hist_kernel<<<1024, 256>>>(dst, E);                           // (1)
    scan1_kernel<<<nsb, SCAN_BLK>>>(N);                           // (2)
    scan2_kernel<<<1, 256>>>(nsb);                                // (3)
    scan3_kernel<<<nsb, SCAN_BLK>>>(N, E);                        // (4)
    scatter_kernel<<<1024, 256>>>(src, dst, ety, E);              // (5)

    int agg_grid = (N + AGG_WARPS * NPW - 1) / (AGG_WARPS * NPW);
    // layer 0 (relu)
    aggregate_kernel<<<agg_grid, 256>>>(c0, 0, N);                          // (6)
    gemm_kernel<<<(N + BM - 1) / BM, 256, SMEM_GEMM>>>(b0, 0, N);           // (7)

    // layer 1 (no activation)
    aggregate_kernel<<<agg_grid, 256>>>(c1, 1, N);                          // (8)
    gemm_kernel<<<(N + BM - 1) / BM, 256, SMEM_GEMM>>>(b1, 1, N);           // (9)

    // DistMult scoring
    score_kernel<<<(T + 7) / 8, 256>>>(head, rel, tail, wrel, out, T);      // (10)
}